// round 1
// baseline (speedup 1.0000x reference)
#include <cuda_runtime.h>
#include <cstdint>

// Problem constants (fixed shapes for this problem instance)
constexpr int Bb  = 2;
constexpr int Cc  = 128;     // in channels
constexpr int Nn  = 50000;   // nodes per batch
constexpr int Mm  = Bb * Nn; // 100000 total nodes
constexpr int Hh  = 2;       // heads
constexpr int FHh = 64;      // per-head features
constexpr int OUT = Hh * FHh; // 128
constexpr int Ee  = 800000;  // edges

constexpr float NEG_SLOPE_GAT = 0.2f;
constexpr float NEG_SLOPE_ACT = 0.01f;
constexpr float LN_EPS = 1e-5f;
constexpr float SOFTMAX_EPS = 1e-16f;

// Scratch (device globals: allocation-free)
__device__ float    g_hl[(size_t)Mm * OUT];   // 51.2 MB source transform
__device__ float    g_hr[(size_t)Mm * OUT];   // 51.2 MB target transform
__device__ float    g_logits[(size_t)Ee * Hh]; // logits, then exp(logit-max) in place
__device__ float    g_denom[(size_t)Mm * Hh];
__device__ unsigned g_segmax[(size_t)Mm * Hh]; // monotone-encoded float max

// ---- monotone float<->uint encoding for atomicMax on floats ----
__device__ __forceinline__ unsigned enc_f(float f) {
    int i = __float_as_int(f);
    return (unsigned)(i ^ ((i >> 31) | 0x80000000));
}
__device__ __forceinline__ float dec_f(unsigned u) {
    int i = (u & 0x80000000u) ? (int)(u ^ 0x80000000u) : (int)(~u);
    return __int_as_float(i);
}

// ---- K0: zero init (out accumulator, denom, segmax) ----
__global__ void k_init(float* __restrict__ out) {
    int i = blockIdx.x * blockDim.x + threadIdx.x;
    int stride = gridDim.x * blockDim.x;
    for (size_t j = i; j < (size_t)Mm * OUT; j += stride) out[j] = 0.f;
    for (int j = i; j < Mm * Hh; j += stride) { g_denom[j] = 0.f; g_segmax[j] = 0u; }
}

// ---- K1: fused transpose + dual GEMM  h = xn @ W + b ----
// blockIdx.y == 0 -> (W_l, b_l, g_hl), == 1 -> (W_r, b_r, g_hr)
// Tile: 64 rows x 128 cols, BK=16, 256 threads, 4x8 register micro-tile.
__global__ void k_gemm(const float* __restrict__ x,
                       const float* __restrict__ Wl, const float* __restrict__ bl,
                       const float* __restrict__ Wr, const float* __restrict__ br) {
    const float* W    = blockIdx.y ? Wr : Wl;
    const float* bias = blockIdx.y ? br : bl;
    float* h          = blockIdx.y ? g_hr : g_hl;

    __shared__ float xs[64][16];
    __shared__ float ws[16][128];

    int tid = threadIdx.x;
    int m0  = blockIdx.x * 64;
    int tx  = tid & 15, ty = tid >> 4;

    float acc[4][8];
    #pragma unroll
    for (int r = 0; r < 4; r++)
        #pragma unroll
        for (int u = 0; u < 8; u++) acc[r][u] = 0.f;

    // x tile loaders: row li (coalesced over n), 4 feature columns each
    int li = tid & 63, lc = tid >> 6;   // lc in 0..3
    int m_l = m0 + li;
    bool rowok = m_l < Mm;
    int bb = rowok ? (m_l / Nn) : 0;
    int nn = rowok ? (m_l % Nn) : 0;
    const float* xrow = x + (size_t)bb * Cc * Nn + nn; // + c*Nn per feature

    // W tile loaders
    int wj = tid & 127, wr_ = tid >> 7; // wr_ in 0..1

    for (int k0 = 0; k0 < Cc; k0 += 16) {
        #pragma unroll
        for (int p = 0; p < 4; p++) {
            int cl = lc * 4 + p;
            xs[li][cl] = rowok ? xrow[(size_t)(k0 + cl) * Nn] : 0.f;
        }
        #pragma unroll
        for (int q = 0; q < 8; q++) {
            int kl = wr_ * 8 + q;
            ws[kl][wj] = W[(size_t)(k0 + kl) * OUT + wj];
        }
        __syncthreads();
        #pragma unroll
        for (int k = 0; k < 16; k++) {
            float a[4], bv[8];
            #pragma unroll
            for (int r = 0; r < 4; r++) a[r] = xs[ty * 4 + r][k];
            #pragma unroll
            for (int u = 0; u < 8; u++) bv[u] = ws[k][tx + 16 * u];
            #pragma unroll
            for (int r = 0; r < 4; r++)
                #pragma unroll
                for (int u = 0; u < 8; u++) acc[r][u] += a[r] * bv[u];
        }
        __syncthreads();
    }

    #pragma unroll
    for (int r = 0; r < 4; r++) {
        int m = m0 + ty * 4 + r;
        if (m < Mm) {
            #pragma unroll
            for (int u = 0; u < 8; u++) {
                int col = tx + 16 * u;
                h[(size_t)m * OUT + col] = acc[r][u] + bias[col];
            }
        }
    }
}

// ---- K2: edge scoring + segment max. One warp per edge. ----
__global__ void k_score(const int* __restrict__ ei, const float* __restrict__ att) {
    int gid  = blockIdx.x * blockDim.x + threadIdx.x;
    int e    = gid >> 5;
    int lane = threadIdx.x & 31;
    if (e >= Ee) return;
    int s = ei[e], d = ei[Ee + e];
    const float* pl = g_hl + (size_t)s * OUT;
    const float* pr = g_hr + (size_t)d * OUT;
    float acc0 = 0.f, acc1 = 0.f;
    #pragma unroll
    for (int k = 0; k < 4; k++) {
        int f = lane + 32 * k;
        float v = pl[f] + pr[f];
        v = v > 0.f ? v : NEG_SLOPE_GAT * v;
        float p = v * att[f];
        if (k < 2) acc0 += p; else acc1 += p;
    }
    #pragma unroll
    for (int off = 16; off > 0; off >>= 1) {
        acc0 += __shfl_xor_sync(0xFFFFFFFFu, acc0, off);
        acc1 += __shfl_xor_sync(0xFFFFFFFFu, acc1, off);
    }
    if (lane == 0) {
        g_logits[(size_t)e * 2]     = acc0;
        g_logits[(size_t)e * 2 + 1] = acc1;
        atomicMax(&g_segmax[(size_t)d * 2],     enc_f(acc0));
        atomicMax(&g_segmax[(size_t)d * 2 + 1], enc_f(acc1));
    }
}

// ---- K3: exp(logit - max) + denominator accumulation. One thread per (edge,head). ----
__global__ void k_exp(const int* __restrict__ ei) {
    int idx = blockIdx.x * blockDim.x + threadIdx.x;
    if (idx >= Ee * Hh) return;
    int e = idx >> 1, h = idx & 1;
    int d = ei[Ee + e];
    float mx = dec_f(g_segmax[(size_t)d * 2 + h]);
    float ex = expf(g_logits[idx] - mx);
    g_logits[idx] = ex;                 // overwrite in place
    atomicAdd(&g_denom[(size_t)d * 2 + h], ex);
}

// ---- K4: weighted scatter-aggregate. One warp per edge, red.global per feature. ----
__global__ void k_agg(const int* __restrict__ ei, float* __restrict__ out) {
    int gid  = blockIdx.x * blockDim.x + threadIdx.x;
    int e    = gid >> 5;
    int lane = threadIdx.x & 31;
    if (e >= Ee) return;
    int s = ei[e], d = ei[Ee + e];
    float a0 = g_logits[(size_t)e * 2]     / (g_denom[(size_t)d * 2]     + SOFTMAX_EPS);
    float a1 = g_logits[(size_t)e * 2 + 1] / (g_denom[(size_t)d * 2 + 1] + SOFTMAX_EPS);
    const float* pl = g_hl + (size_t)s * OUT;
    float* po = out + (size_t)d * OUT;
    #pragma unroll
    for (int k = 0; k < 4; k++) {
        int f = lane + 32 * k;
        float al = (k < 2) ? a0 : a1;
        atomicAdd(&po[f], al * pl[f]);
    }
}

// ---- K5: bias + LayerNorm + LeakyReLU. One warp per node, in-place on out. ----
__global__ void k_ln(float* __restrict__ out, const float* __restrict__ bias,
                     const float* __restrict__ gamma, const float* __restrict__ beta) {
    int gid  = blockIdx.x * blockDim.x + threadIdx.x;
    int m    = gid >> 5;
    int lane = threadIdx.x & 31;
    if (m >= Mm) return;
    float v[4];
    float s = 0.f, s2 = 0.f;
    #pragma unroll
    for (int k = 0; k < 4; k++) {
        int f = lane + 32 * k;
        v[k] = out[(size_t)m * OUT + f] + bias[f];
        s  += v[k];
        s2 += v[k] * v[k];
    }
    #pragma unroll
    for (int off = 16; off > 0; off >>= 1) {
        s  += __shfl_xor_sync(0xFFFFFFFFu, s,  off);
        s2 += __shfl_xor_sync(0xFFFFFFFFu, s2, off);
    }
    float mu  = s * (1.f / OUT);
    float var = s2 * (1.f / OUT) - mu * mu;
    float inv = rsqrtf(var + LN_EPS);
    #pragma unroll
    for (int k = 0; k < 4; k++) {
        int f = lane + 32 * k;
        float y = (v[k] - mu) * inv * gamma[f] + beta[f];
        out[(size_t)m * OUT + f] = y > 0.f ? y : NEG_SLOPE_ACT * y;
    }
}

extern "C" void kernel_launch(void* const* d_in, const int* in_sizes, int n_in,
                              void* d_out, int out_size) {
    const float* x        = (const float*)d_in[0];
    const int*   ei       = (const int*)  d_in[1];
    const float* Wl       = (const float*)d_in[2];
    const float* bl       = (const float*)d_in[3];
    const float* Wr       = (const float*)d_in[4];
    const float* br       = (const float*)d_in[5];
    const float* att      = (const float*)d_in[6];
    const float* bias_gat = (const float*)d_in[7];
    const float* gamma    = (const float*)d_in[8];
    const float* beta     = (const float*)d_in[9];
    float* out = (float*)d_out;

    (void)in_sizes; (void)n_in; (void)out_size;

    k_init<<<1024, 256>>>(out);

    dim3 ggrid((Mm + 63) / 64, 2);
    k_gemm<<<ggrid, 256>>>(x, Wl, bl, Wr, br);

    int warps_e_blocks = (Ee * 32 + 255) / 256;
    k_score<<<warps_e_blocks, 256>>>(ei, att);
    k_exp<<<(Ee * Hh + 255) / 256, 256>>>(ei);
    k_agg<<<warps_e_blocks, 256>>>(ei, out);

    k_ln<<<(Mm * 32 + 255) / 256, 256>>>(out, bias_gat, gamma, beta);
}

// round 2
// speedup vs baseline: 1.4091x; 1.4091x over previous
#include <cuda_runtime.h>
#include <cstdint>

// Problem constants
constexpr int Bb  = 2;
constexpr int Cc  = 128;
constexpr int Nn  = 50000;
constexpr int Mm  = Bb * Nn;
constexpr int Hh  = 2;
constexpr int FHh = 64;
constexpr int OUT = Hh * FHh; // 128
constexpr int Ee  = 800000;

constexpr float NEG_SLOPE_GAT = 0.2f;
constexpr float NEG_SLOPE_ACT = 0.01f;
constexpr float LN_EPS = 1e-5f;
constexpr float SOFTMAX_EPS = 1e-16f;

// Scratch (device globals: allocation-free)
__device__ float    g_hl[(size_t)Mm * OUT];
__device__ float    g_hr[(size_t)Mm * OUT];
__device__ float    g_logits[(size_t)Ee * Hh];
__device__ float    g_denom[(size_t)Mm * Hh];
__device__ unsigned g_segmax[(size_t)Mm * Hh];

__device__ __forceinline__ unsigned enc_f(float f) {
    int i = __float_as_int(f);
    return (unsigned)(i ^ ((i >> 31) | 0x80000000));
}
__device__ __forceinline__ float dec_f(unsigned u) {
    int i = (u & 0x80000000u) ? (int)(u ^ 0x80000000u) : (int)(~u);
    return __int_as_float(i);
}
__device__ __forceinline__ uint32_t f2tf32(float f) {
    uint32_t u;
    asm("cvt.rna.tf32.f32 %0, %1;" : "=r"(u) : "f"(f));
    return u;
}

// ---- K0: zero init ----
__global__ void k_init(float4* __restrict__ out) {
    int i = blockIdx.x * blockDim.x + threadIdx.x;
    int stride = gridDim.x * blockDim.x;
    const float4 z = {0.f, 0.f, 0.f, 0.f};
    for (size_t j = i; j < (size_t)Mm * OUT / 4; j += stride) out[j] = z;
    for (int j = i; j < Mm * Hh; j += stride) { g_denom[j] = 0.f; g_segmax[j] = 0u; }
}

// ---- K1: fused transpose + dual GEMM via tf32 mma.sync ----
// Tile 128x128, BK=32, 256 threads (8 warps, 4x2), warp = 32x64 (2x8 mma tiles).
constexpr int BM = 128, BN = 128, BK = 32;

__global__ void __launch_bounds__(256, 2)
k_gemm_tc(const float* __restrict__ x,
          const float* __restrict__ Wl, const float* __restrict__ bl,
          const float* __restrict__ Wr, const float* __restrict__ br) {
    const float* W    = blockIdx.y ? Wr : Wl;
    const float* bias = blockIdx.y ? br : bl;
    float* h          = blockIdx.y ? g_hr : g_hl;

    __shared__ uint32_t xs[BM][BK + 4];   // A tf32 bits; pad 4 -> conflict-free frag loads
    __shared__ uint32_t ws[BK][BN + 12];  // B tf32 bits; pad 12 -> conflict-free frag loads

    int tid  = threadIdx.x;
    int lane = tid & 31;
    int wid  = tid >> 5;
    int wm   = wid & 3;   // m group (32 rows)
    int wn   = wid >> 2;  // n group (64 cols)
    int lrow = lane >> 2; // 0..7
    int lcol = lane & 3;  // 0..3

    int m0 = blockIdx.x * BM;

    // A stage loader: m per thread (coalesced over n), 16 k-cols each
    int ml   = tid & 127;
    int kc   = tid >> 7;  // 0..1
    int m_l  = m0 + ml;
    bool rowok = m_l < Mm;
    int bb = rowok ? (m_l / Nn) : 0;
    int nn = rowok ? (m_l % Nn) : 0;
    const float* xrow = x + (size_t)bb * Cc * Nn + nn;

    float acc[2][8][4];
    #pragma unroll
    for (int mt = 0; mt < 2; mt++)
        #pragma unroll
        for (int nt = 0; nt < 8; nt++)
            #pragma unroll
            for (int q = 0; q < 4; q++) acc[mt][nt][q] = 0.f;

    for (int k0 = 0; k0 < Cc; k0 += BK) {
        // stage A
        #pragma unroll
        for (int k = kc; k < BK; k += 2) {
            float v = rowok ? xrow[(size_t)(k0 + k) * Nn] : 0.f;
            xs[ml][k] = f2tf32(v);
        }
        // stage B (W is (C, OUT) row-major)
        #pragma unroll
        for (int k = kc; k < BK; k += 2) {
            ws[k][ml] = f2tf32(W[(size_t)(k0 + k) * OUT + ml]);
        }
        __syncthreads();

        #pragma unroll
        for (int kk = 0; kk < 4; kk++) {
            int kb = kk * 8;
            uint32_t af[2][4];
            #pragma unroll
            for (int mt = 0; mt < 2; mt++) {
                int r = wm * 32 + mt * 16 + lrow;
                af[mt][0] = xs[r][kb + lcol];
                af[mt][1] = xs[r + 8][kb + lcol];
                af[mt][2] = xs[r][kb + lcol + 4];
                af[mt][3] = xs[r + 8][kb + lcol + 4];
            }
            #pragma unroll
            for (int nt = 0; nt < 8; nt++) {
                int cn = wn * 64 + nt * 8 + lrow;
                uint32_t b0 = ws[kb + lcol][cn];
                uint32_t b1 = ws[kb + lcol + 4][cn];
                #pragma unroll
                for (int mt = 0; mt < 2; mt++) {
                    asm volatile(
                        "mma.sync.aligned.m16n8k8.row.col.f32.tf32.tf32.f32 "
                        "{%0,%1,%2,%3}, {%4,%5,%6,%7}, {%8,%9}, {%0,%1,%2,%3};\n"
                        : "+f"(acc[mt][nt][0]), "+f"(acc[mt][nt][1]),
                          "+f"(acc[mt][nt][2]), "+f"(acc[mt][nt][3])
                        : "r"(af[mt][0]), "r"(af[mt][1]), "r"(af[mt][2]), "r"(af[mt][3]),
                          "r"(b0), "r"(b1));
                }
            }
        }
        __syncthreads();
    }

    // epilogue: add bias, store float2 pairs
    #pragma unroll
    for (int mt = 0; mt < 2; mt++) {
        #pragma unroll
        for (int nt = 0; nt < 8; nt++) {
            int row = m0 + wm * 32 + mt * 16 + lrow;
            int col = wn * 64 + nt * 8 + lcol * 2;
            float bcol0 = bias[col], bcol1 = bias[col + 1];
            if (row < Mm) {
                float2 v = {acc[mt][nt][0] + bcol0, acc[mt][nt][1] + bcol1};
                *(float2*)&h[(size_t)row * OUT + col] = v;
            }
            if (row + 8 < Mm) {
                float2 v = {acc[mt][nt][2] + bcol0, acc[mt][nt][3] + bcol1};
                *(float2*)&h[(size_t)(row + 8) * OUT + col] = v;
            }
        }
    }
}

// ---- K2: edge scoring + segment max. One warp per edge, float4 lanes. ----
__global__ void k_score(const int* __restrict__ ei, const float* __restrict__ att) {
    int gid  = blockIdx.x * blockDim.x + threadIdx.x;
    int e    = gid >> 5;
    int lane = threadIdx.x & 31;
    if (e >= Ee) return;
    int s = ei[e], d = ei[Ee + e];
    const float4 l4 = *(const float4*)(g_hl + (size_t)s * OUT + lane * 4);
    const float4 r4 = *(const float4*)(g_hr + (size_t)d * OUT + lane * 4);
    const float4 a4 = *(const float4*)(att + lane * 4);
    float vx = l4.x + r4.x, vy = l4.y + r4.y, vz = l4.z + r4.z, vw = l4.w + r4.w;
    vx = vx > 0.f ? vx : NEG_SLOPE_GAT * vx;
    vy = vy > 0.f ? vy : NEG_SLOPE_GAT * vy;
    vz = vz > 0.f ? vz : NEG_SLOPE_GAT * vz;
    vw = vw > 0.f ? vw : NEG_SLOPE_GAT * vw;
    float p = vx * a4.x + vy * a4.y + vz * a4.z + vw * a4.w;
    // reduce within 16-lane halves (lanes 0-15: head 0, 16-31: head 1)
    #pragma unroll
    for (int off = 8; off > 0; off >>= 1)
        p += __shfl_xor_sync(0xFFFFFFFFu, p, off);
    float other = __shfl_sync(0xFFFFFFFFu, p, 16);
    if (lane == 0) {
        g_logits[(size_t)e * 2]     = p;
        g_logits[(size_t)e * 2 + 1] = other;
        atomicMax(&g_segmax[(size_t)d * 2],     enc_f(p));
        atomicMax(&g_segmax[(size_t)d * 2 + 1], enc_f(other));
    }
}

// ---- K3: exp(logit - max) + denominator. One thread per (edge,head). ----
__global__ void k_exp(const int* __restrict__ ei) {
    int idx = blockIdx.x * blockDim.x + threadIdx.x;
    if (idx >= Ee * Hh) return;
    int e = idx >> 1, hh = idx & 1;
    int d = ei[Ee + e];
    float mx = dec_f(g_segmax[(size_t)d * 2 + hh]);
    float ex = expf(g_logits[idx] - mx);
    g_logits[idx] = ex;
    atomicAdd(&g_denom[(size_t)d * 2 + hh], ex);
}

// ---- K4: weighted scatter-aggregate. One warp per edge, vector red. ----
__global__ void k_agg(const int* __restrict__ ei, float* __restrict__ out) {
    int gid  = blockIdx.x * blockDim.x + threadIdx.x;
    int e    = gid >> 5;
    int lane = threadIdx.x & 31;
    if (e >= Ee) return;
    int s = ei[e], d = ei[Ee + e];
    int hh = lane >> 4;
    float alpha = g_logits[(size_t)e * 2 + hh] /
                  (g_denom[(size_t)d * 2 + hh] + SOFTMAX_EPS);
    const float4 l4 = *(const float4*)(g_hl + (size_t)s * OUT + lane * 4);
    float* po = out + (size_t)d * OUT + lane * 4;
    asm volatile("red.global.add.v4.f32 [%0], {%1, %2, %3, %4};"
                 :: "l"(po),
                    "f"(alpha * l4.x), "f"(alpha * l4.y),
                    "f"(alpha * l4.z), "f"(alpha * l4.w)
                 : "memory");
}

// ---- K5: bias + LayerNorm + LeakyReLU. One warp per node, float4. ----
__global__ void k_ln(float* __restrict__ out, const float* __restrict__ bias,
                     const float* __restrict__ gamma, const float* __restrict__ beta) {
    int gid  = blockIdx.x * blockDim.x + threadIdx.x;
    int m    = gid >> 5;
    int lane = threadIdx.x & 31;
    if (m >= Mm) return;
    float* row = out + (size_t)m * OUT;
    float4 v = *(float4*)(row + lane * 4);
    const float4 b4 = *(const float4*)(bias + lane * 4);
    v.x += b4.x; v.y += b4.y; v.z += b4.z; v.w += b4.w;
    float s  = v.x + v.y + v.z + v.w;
    float s2 = v.x * v.x + v.y * v.y + v.z * v.z + v.w * v.w;
    #pragma unroll
    for (int off = 16; off > 0; off >>= 1) {
        s  += __shfl_xor_sync(0xFFFFFFFFu, s,  off);
        s2 += __shfl_xor_sync(0xFFFFFFFFu, s2, off);
    }
    float mu  = s * (1.f / OUT);
    float var = s2 * (1.f / OUT) - mu * mu;
    float inv = rsqrtf(var + LN_EPS);
    const float4 g4 = *(const float4*)(gamma + lane * 4);
    const float4 t4 = *(const float4*)(beta + lane * 4);
    float4 y;
    y.x = (v.x - mu) * inv * g4.x + t4.x;
    y.y = (v.y - mu) * inv * g4.y + t4.y;
    y.z = (v.z - mu) * inv * g4.z + t4.z;
    y.w = (v.w - mu) * inv * g4.w + t4.w;
    y.x = y.x > 0.f ? y.x : NEG_SLOPE_ACT * y.x;
    y.y = y.y > 0.f ? y.y : NEG_SLOPE_ACT * y.y;
    y.z = y.z > 0.f ? y.z : NEG_SLOPE_ACT * y.z;
    y.w = y.w > 0.f ? y.w : NEG_SLOPE_ACT * y.w;
    *(float4*)(row + lane * 4) = y;
}

extern "C" void kernel_launch(void* const* d_in, const int* in_sizes, int n_in,
                              void* d_out, int out_size) {
    const float* x        = (const float*)d_in[0];
    const int*   ei       = (const int*)  d_in[1];
    const float* Wl       = (const float*)d_in[2];
    const float* bl       = (const float*)d_in[3];
    const float* Wr       = (const float*)d_in[4];
    const float* br       = (const float*)d_in[5];
    const float* att      = (const float*)d_in[6];
    const float* bias_gat = (const float*)d_in[7];
    const float* gamma    = (const float*)d_in[8];
    const float* beta     = (const float*)d_in[9];
    float* out = (float*)d_out;

    (void)in_sizes; (void)n_in; (void)out_size;

    k_init<<<1024, 256>>>((float4*)out);

    dim3 ggrid((Mm + BM - 1) / BM, 2);
    k_gemm_tc<<<ggrid, 256>>>(x, Wl, bl, Wr, br);

    int warps_e_blocks = (Ee * 32 + 255) / 256;
    k_score<<<warps_e_blocks, 256>>>(ei, att);
    k_exp<<<(Ee * Hh + 255) / 256, 256>>>(ei);
    k_agg<<<warps_e_blocks, 256>>>(ei, out);

    k_ln<<<(Mm * 32 + 255) / 256, 256>>>(out, bias_gat, gamma, beta);
}